// round 1
// baseline (speedup 1.0000x reference)
#include <cuda_runtime.h>

// Problem constants
#define Bb 2
#define Ss 2048
#define Dd 1024
#define Hh 16
#define DKk 64

// Scratch (allocation-free rule: __device__ globals)
__device__ float g_q [(size_t)Bb * Ss * Dd];
__device__ float g_k [(size_t)Bb * Ss * Dd];
__device__ float g_v [(size_t)Bb * Ss * Dd];
__device__ float g_ao[(size_t)Bb * Ss * Dd];

// ---------------------------------------------------------------------------
// GEMM: C[M,N] = A[M,K] * W[N,K]^T   (row-major A, row-major W)
// 128x128 tile, BK=16, 256 threads, 8x8 micro-tile, transposed smem tiles.
// ---------------------------------------------------------------------------
__global__ void __launch_bounds__(256) gemm_nt(const float* __restrict__ A,
                                               const float* __restrict__ W,
                                               float* __restrict__ C,
                                               int M, int N, int K) {
    __shared__ float Ast[16][128];
    __shared__ float Wst[16][128];

    const int tid = threadIdx.x;
    const int tx = tid & 15;
    const int ty = tid >> 4;
    const int m0 = blockIdx.y * 128;
    const int n0 = blockIdx.x * 128;

    const int lr = tid >> 1;        // 0..127: row within tile
    const int lc = (tid & 1) * 8;   // 0 or 8: col offset within BK=16

    const float* Ap = A + (size_t)(m0 + lr) * K + lc;
    const float* Wp = W + (size_t)(n0 + lr) * K + lc;

    float acc[8][8];
#pragma unroll
    for (int i = 0; i < 8; i++)
#pragma unroll
        for (int j = 0; j < 8; j++) acc[i][j] = 0.0f;

    for (int k0 = 0; k0 < K; k0 += 16) {
        float4 a0 = *(const float4*)(Ap + k0);
        float4 a1 = *(const float4*)(Ap + k0 + 4);
        float4 w0 = *(const float4*)(Wp + k0);
        float4 w1 = *(const float4*)(Wp + k0 + 4);
        Ast[lc + 0][lr] = a0.x; Ast[lc + 1][lr] = a0.y;
        Ast[lc + 2][lr] = a0.z; Ast[lc + 3][lr] = a0.w;
        Ast[lc + 4][lr] = a1.x; Ast[lc + 5][lr] = a1.y;
        Ast[lc + 6][lr] = a1.z; Ast[lc + 7][lr] = a1.w;
        Wst[lc + 0][lr] = w0.x; Wst[lc + 1][lr] = w0.y;
        Wst[lc + 2][lr] = w0.z; Wst[lc + 3][lr] = w0.w;
        Wst[lc + 4][lr] = w1.x; Wst[lc + 5][lr] = w1.y;
        Wst[lc + 6][lr] = w1.z; Wst[lc + 7][lr] = w1.w;
        __syncthreads();

#pragma unroll
        for (int kk = 0; kk < 16; kk++) {
            float a[8], w[8];
            *(float4*)&a[0] = *(const float4*)&Ast[kk][ty * 8];
            *(float4*)&a[4] = *(const float4*)&Ast[kk][ty * 8 + 4];
            *(float4*)&w[0] = *(const float4*)&Wst[kk][tx * 8];
            *(float4*)&w[4] = *(const float4*)&Wst[kk][tx * 8 + 4];
#pragma unroll
            for (int i = 0; i < 8; i++)
#pragma unroll
                for (int j = 0; j < 8; j++)
                    acc[i][j] += a[i] * w[j];
        }
        __syncthreads();
    }

#pragma unroll
    for (int i = 0; i < 8; i++) {
        float* Cp = C + (size_t)(m0 + ty * 8 + i) * N + n0 + tx * 8;
        *(float4*)(Cp)     = make_float4(acc[i][0], acc[i][1], acc[i][2], acc[i][3]);
        *(float4*)(Cp + 4) = make_float4(acc[i][4], acc[i][5], acc[i][6], acc[i][7]);
    }
}

// ---------------------------------------------------------------------------
// RoPE in-place on q and k.  Pairs (2i, 2i+1) within each head dim.
// ---------------------------------------------------------------------------
__global__ void __launch_bounds__(256) rope_kernel(float* __restrict__ q,
                                                   float* __restrict__ k,
                                                   const float* __restrict__ cs,
                                                   const float* __restrict__ sn) {
    int idx = blockIdx.x * blockDim.x + threadIdx.x;   // over Bb*Ss*Hh*32
    int i = idx & 31;
    int h = (idx >> 5) & (Hh - 1);
    int s = (idx >> 9) & (Ss - 1);
    int b = idx >> 20;
    if (b >= Bb) return;

    float c  = cs[s * 32 + i];
    float sv = sn[s * 32 + i];
    size_t base = ((((size_t)b * Ss + s) * Hh + h) * DKk) + 2 * i;

    float q0 = q[base], q1 = q[base + 1];
    q[base]     = q0 * c - q1 * sv;
    q[base + 1] = q0 * sv + q1 * c;
    float k0 = k[base], k1 = k[base + 1];
    k[base]     = k0 * c - k1 * sv;
    k[base + 1] = k0 * sv + k1 * c;
}

// ---------------------------------------------------------------------------
// Flash-style causal attention.
// One CTA per (b, h, 64-query tile).  logits = q.k / 64, causal mask.
// smem: qs 16KB + kv 16KB (K transposed, then reused for V) + ps 16KB = 48KB.
// ---------------------------------------------------------------------------
__global__ void __launch_bounds__(256) flash_kernel(const float* __restrict__ Q,
                                                    const float* __restrict__ Kg,
                                                    const float* __restrict__ Vg,
                                                    float* __restrict__ Og) {
    __shared__ float qs[64][64];   // qs[row][dk]
    __shared__ float kv[64][64];   // K phase: kv[dk][key]; V phase: kv[key][dk]
    __shared__ float ps[64][64];   // probabilities ps[row][key]

    const int tid = threadIdx.x;
    const int tx = tid & 15;
    const int ty = tid >> 4;
    const int tx4 = tx * 4, ty4 = ty * 4;

    const int qt = blockIdx.x & 31;
    const int h  = (blockIdx.x >> 5) & (Hh - 1);
    const int b  = blockIdx.x >> 9;

    // Load Q tile
    {
        int r = tid >> 2, vb = tid & 3;
        const float* qp = Q + (((size_t)b * Ss + qt * 64 + r) * Hh + h) * DKk;
#pragma unroll
        for (int v = vb; v < 16; v += 4)
            *(float4*)&qs[r][v * 4] = *(const float4*)(qp + v * 4);
    }

    float m_i[4], l_i[4], o[4][4];
#pragma unroll
    for (int i = 0; i < 4; i++) {
        m_i[i] = -1e30f; l_i[i] = 0.0f;
#pragma unroll
        for (int j = 0; j < 4; j++) o[i][j] = 0.0f;
    }
    __syncthreads();

    for (int kt = 0; kt <= qt; kt++) {
        const int k0 = kt * 64;
        // Load K tile transposed: kv[dk][key]
        {
            int r = tid >> 2, vb = tid & 3;
            const float* kp = Kg + (((size_t)b * Ss + k0 + r) * Hh + h) * DKk;
#pragma unroll
            for (int v = vb; v < 16; v += 4) {
                float4 t4 = *(const float4*)(kp + v * 4);
                kv[v * 4 + 0][r] = t4.x;
                kv[v * 4 + 1][r] = t4.y;
                kv[v * 4 + 2][r] = t4.z;
                kv[v * 4 + 3][r] = t4.w;
            }
        }
        __syncthreads();

        // S = Q * K^T  (4x4 micro-tile per thread)
        float s[4][4];
#pragma unroll
        for (int i = 0; i < 4; i++)
#pragma unroll
            for (int j = 0; j < 4; j++) s[i][j] = 0.0f;

#pragma unroll 16
        for (int dk = 0; dk < 64; dk++) {
            float4 b4 = *(const float4*)&kv[dk][tx4];
            float a0 = qs[ty4 + 0][dk];
            float a1 = qs[ty4 + 1][dk];
            float a2 = qs[ty4 + 2][dk];
            float a3 = qs[ty4 + 3][dk];
            s[0][0] += a0 * b4.x; s[0][1] += a0 * b4.y; s[0][2] += a0 * b4.z; s[0][3] += a0 * b4.w;
            s[1][0] += a1 * b4.x; s[1][1] += a1 * b4.y; s[1][2] += a1 * b4.z; s[1][3] += a1 * b4.w;
            s[2][0] += a2 * b4.x; s[2][1] += a2 * b4.y; s[2][2] += a2 * b4.z; s[2][3] += a2 * b4.w;
            s[3][0] += a3 * b4.x; s[3][1] += a3 * b4.y; s[3][2] += a3 * b4.z; s[3][3] += a3 * b4.w;
        }

        // Scale (ref: softmax((qk*inv_sqrt + mask) * inv_sqrt) = softmax(qk/64))
        const bool diag = (kt == qt);
#pragma unroll
        for (int i = 0; i < 4; i++) {
            int rg = qt * 64 + ty4 + i;
#pragma unroll
            for (int j = 0; j < 4; j++) {
                s[i][j] *= (1.0f / 64.0f);
                if (diag && (k0 + tx4 + j) > rg) s[i][j] = -1e30f;
            }
        }

        // Online softmax update; row reductions across the 16-lane row group.
#pragma unroll
        for (int i = 0; i < 4; i++) {
            float mx = fmaxf(fmaxf(s[i][0], s[i][1]), fmaxf(s[i][2], s[i][3]));
#pragma unroll
            for (int off = 1; off < 16; off <<= 1)
                mx = fmaxf(mx, __shfl_xor_sync(0xffffffffu, mx, off));
            float mnew = fmaxf(m_i[i], mx);
            float corr = __expf(m_i[i] - mnew);
            float rs = 0.0f;
#pragma unroll
            for (int j = 0; j < 4; j++) {
                float p = __expf(s[i][j] - mnew);
                s[i][j] = p;
                rs += p;
            }
#pragma unroll
            for (int off = 1; off < 16; off <<= 1)
                rs += __shfl_xor_sync(0xffffffffu, rs, off);
            l_i[i] = l_i[i] * corr + rs;
            m_i[i] = mnew;
            o[i][0] *= corr; o[i][1] *= corr; o[i][2] *= corr; o[i][3] *= corr;
            *(float4*)&ps[ty4 + i][tx4] = make_float4(s[i][0], s[i][1], s[i][2], s[i][3]);
        }
        __syncthreads();   // everyone done reading K and writing P

        // Load V tile (normal layout): kv[key][dk]
        {
            int r = tid >> 2, vb = tid & 3;
            const float* vp = Vg + (((size_t)b * Ss + k0 + r) * Hh + h) * DKk;
#pragma unroll
            for (int v = vb; v < 16; v += 4)
                *(float4*)&kv[r][v * 4] = *(const float4*)(vp + v * 4);
        }
        __syncthreads();

        // O += P * V
#pragma unroll 16
        for (int kk = 0; kk < 64; kk++) {
            float4 v4 = *(const float4*)&kv[kk][tx4];
            float p0 = ps[ty4 + 0][kk];
            float p1 = ps[ty4 + 1][kk];
            float p2 = ps[ty4 + 2][kk];
            float p3 = ps[ty4 + 3][kk];
            o[0][0] += p0 * v4.x; o[0][1] += p0 * v4.y; o[0][2] += p0 * v4.z; o[0][3] += p0 * v4.w;
            o[1][0] += p1 * v4.x; o[1][1] += p1 * v4.y; o[1][2] += p1 * v4.z; o[1][3] += p1 * v4.w;
            o[2][0] += p2 * v4.x; o[2][1] += p2 * v4.y; o[2][2] += p2 * v4.z; o[2][3] += p2 * v4.w;
            o[3][0] += p3 * v4.x; o[3][1] += p3 * v4.y; o[3][2] += p3 * v4.z; o[3][3] += p3 * v4.w;
        }
        __syncthreads();   // before next iteration overwrites kv / ps
    }

    // Normalize and write out (layout [B,S,H,DK] == [B,S,D])
#pragma unroll
    for (int i = 0; i < 4; i++) {
        float inv = 1.0f / l_i[i];
        float* op = Og + (((size_t)b * Ss + qt * 64 + ty4 + i) * Hh + h) * DKk + tx4;
        *(float4*)op = make_float4(o[i][0] * inv, o[i][1] * inv, o[i][2] * inv, o[i][3] * inv);
    }
}

// ---------------------------------------------------------------------------
// Launch: x,fc,fs,mask,wq,wk,wv,wo  (mask is analytic causal -> unused)
// ---------------------------------------------------------------------------
extern "C" void kernel_launch(void* const* d_in, const int* in_sizes, int n_in,
                              void* d_out, int out_size) {
    const float* x  = (const float*)d_in[0];
    const float* fc = (const float*)d_in[1];
    const float* fs = (const float*)d_in[2];
    const float* wq = (const float*)d_in[4];
    const float* wk = (const float*)d_in[5];
    const float* wv = (const float*)d_in[6];
    const float* wo = (const float*)d_in[7];
    float* out = (float*)d_out;

    float *q, *k, *v, *ao;
    cudaGetSymbolAddress((void**)&q,  g_q);
    cudaGetSymbolAddress((void**)&k,  g_k);
    cudaGetSymbolAddress((void**)&v,  g_v);
    cudaGetSymbolAddress((void**)&ao, g_ao);

    const int M = Bb * Ss;   // 4096
    const int N = Dd;        // 1024
    const int K = Dd;        // 1024
    dim3 gg(N / 128, M / 128);

    gemm_nt<<<gg, 256>>>(x, wq, q, M, N, K);
    gemm_nt<<<gg, 256>>>(x, wk, k, M, N, K);
    gemm_nt<<<gg, 256>>>(x, wv, v, M, N, K);

    rope_kernel<<<(Bb * Ss * Hh * 32) / 256, 256>>>(q, k, fc, fs);

    flash_kernel<<<Bb * Hh * (Ss / 64), 256>>>(q, k, v, ao);

    gemm_nt<<<gg, 256>>>(ao, wo, out, M, N, K);
}

// round 5
// speedup vs baseline: 1.0548x; 1.0548x over previous
#include <cuda_runtime.h>

// Problem constants
#define Bb 2
#define Ss 2048
#define Dd 1024
#define Hh 16
#define DKk 64

typedef unsigned long long ull;

// Scratch (allocation-free rule: __device__ globals)
__device__ float g_q [(size_t)Bb * Ss * Dd];
__device__ float g_k [(size_t)Bb * Ss * Dd];
__device__ float g_v [(size_t)Bb * Ss * Dd];
__device__ float g_ao[(size_t)Bb * Ss * Dd];

// ---------------------------------------------------------------------------
// Packed f32x2 helpers (Blackwell): one FFMA2 issue = 2 lane-FMAs.
// Pair layout: low 32 bits = first (even) float — matches consecutive floats
// in memory, so packed operands are free reinterprets of float pairs.
// ---------------------------------------------------------------------------
__device__ __forceinline__ ull dup2(float x) {
    ull r;
    asm("mov.b64 %0, {%1, %1};" : "=l"(r) : "r"(__float_as_uint(x)));
    return r;
}
__device__ __forceinline__ void ffma2(ull& d, ull a, ull b) {
    asm("fma.rn.f32x2 %0, %1, %2, %0;" : "+l"(d) : "l"(a), "l"(b));
}
__device__ __forceinline__ ull mul2(ull a, ull b) {
    ull r;
    asm("mul.rn.f32x2 %0, %1, %2;" : "=l"(r) : "l"(a), "l"(b));
    return r;
}
__device__ __forceinline__ float2 up2(ull v) {
    unsigned lo, hi;
    asm("mov.b64 {%0, %1}, %2;" : "=r"(lo), "=r"(hi) : "l"(v));
    return make_float2(__uint_as_float(lo), __uint_as_float(hi));
}

// ---------------------------------------------------------------------------
// GEMM core: C[M,N] = A[M,1024] * W[N,1024]^T, 128x128 tile, BK=16,
// 256 threads, 8x8 micro-tile via f32x2, register prefetch double-buffer.
// acc2[i][jj] packs output cols (n0+tx*8+2jj, +2jj+1) for row m0+ty*8+i.
// ---------------------------------------------------------------------------
__device__ __forceinline__ void gemm_core(const float* __restrict__ A,
                                          const float* __restrict__ W,
                                          int m0, int n0, int tid,
                                          float (*Ast)[128], float (*Wst)[128],
                                          ull acc2[8][4]) {
    const int tx = tid & 15;
    const int ty = tid >> 4;
    const int lr = tid >> 1;        // 0..127: row within tile
    const int lc = (tid & 1) * 8;   // 0 or 8: k-offset within BK=16

    const float* Ap = A + (size_t)(m0 + lr) * Dd + lc;
    const float* Wp = W + (size_t)(n0 + lr) * Dd + lc;

#pragma unroll
    for (int i = 0; i < 8; i++)
#pragma unroll
        for (int j = 0; j < 4; j++) acc2[i][j] = 0ull;

    // prefetch k-block 0
    float4 a0 = *(const float4*)(Ap);
    float4 a1 = *(const float4*)(Ap + 4);
    float4 w0 = *(const float4*)(Wp);
    float4 w1 = *(const float4*)(Wp + 4);

    for (int k0 = 0; k0 < Dd; k0 += 16) {
        Ast[lc + 0][lr] = a0.x; Ast[lc + 1][lr] = a0.y;
        Ast[lc + 2][lr] = a0.z; Ast[lc + 3][lr] = a0.w;
        Ast[lc + 4][lr] = a1.x; Ast[lc + 5][lr] = a1.y;
        Ast[lc + 6][lr] = a1.z; Ast[lc + 7][lr] = a1.w;
        Wst[lc + 0][lr] = w0.x; Wst[lc + 1][lr] = w0.y;
        Wst[lc + 2][lr] = w0.z; Wst[lc + 3][lr] = w0.w;
        Wst[lc + 4][lr] = w1.x; Wst[lc + 5][lr] = w1.y;
        Wst[lc + 6][lr] = w1.z; Wst[lc + 7][lr] = w1.w;
        __syncthreads();

        // prefetch next k-block while computing this one
        if (k0 + 16 < Dd) {
            a0 = *(const float4*)(Ap + k0 + 16);
            a1 = *(const float4*)(Ap + k0 + 20);
            w0 = *(const float4*)(Wp + k0 + 16);
            w1 = *(const float4*)(Wp + k0 + 20);
        }

#pragma unroll
        for (int kk = 0; kk < 16; kk++) {
            float a[8];
            *(float4*)&a[0] = *(const float4*)&Ast[kk][ty * 8];
            *(float4*)&a[4] = *(const float4*)&Ast[kk][ty * 8 + 4];
            ulonglong2 wp0 = *(const ulonglong2*)&Wst[kk][tx * 8];
            ulonglong2 wp1 = *(const ulonglong2*)&Wst[kk][tx * 8 + 4];
#pragma unroll
            for (int i = 0; i < 8; i++) {
                ull ad = dup2(a[i]);
                ffma2(acc2[i][0], ad, wp0.x);
                ffma2(acc2[i][1], ad, wp0.y);
                ffma2(acc2[i][2], ad, wp1.x);
                ffma2(acc2[i][3], ad, wp1.y);
            }
        }
        __syncthreads();
    }
}

// ---------------------------------------------------------------------------
// Fused QKV projection + RoPE epilogue.  blockIdx.z: 0=Q(rope) 1=K(rope) 2=V.
// ---------------------------------------------------------------------------
__global__ void __launch_bounds__(256, 2) gemm_qkv(const float* __restrict__ x,
                                                   const float* __restrict__ wq,
                                                   const float* __restrict__ wk,
                                                   const float* __restrict__ wv,
                                                   float* __restrict__ q,
                                                   float* __restrict__ k,
                                                   float* __restrict__ v,
                                                   const float* __restrict__ cs,
                                                   const float* __restrict__ sn) {
    __shared__ float Ast[16][128];
    __shared__ float Wst[16][128];

    const int z = blockIdx.z;
    const float* W = (z == 0) ? wq : ((z == 1) ? wk : wv);
    float* C = (z == 0) ? q : ((z == 1) ? k : v);

    const int tid = threadIdx.x;
    const int tx = tid & 15;
    const int ty = tid >> 4;
    const int m0 = blockIdx.y * 128;
    const int n0 = blockIdx.x * 128;

    ull acc2[8][4];
    gemm_core(x, W, m0, n0, tid, Ast, Wst, acc2);

    const bool dorope = (z < 2);
    const int p0 = (tx & 7) * 4;   // pair base within head (cols are head-aligned)

#pragma unroll
    for (int i = 0; i < 8; i++) {
        const int m = m0 + ty * 8 + i;
        float2 v0 = up2(acc2[i][0]);
        float2 v1 = up2(acc2[i][1]);
        float2 v2 = up2(acc2[i][2]);
        float2 v3 = up2(acc2[i][3]);
        if (dorope) {
            const int s = m & (Ss - 1);
            float4 c4 = *(const float4*)(cs + (size_t)s * 32 + p0);
            float4 s4 = *(const float4*)(sn + (size_t)s * 32 + p0);
            float t;
            t = v0.x; v0.x = t * c4.x - v0.y * s4.x; v0.y = t * s4.x + v0.y * c4.x;
            t = v1.x; v1.x = t * c4.y - v1.y * s4.y; v1.y = t * s4.y + v1.y * c4.y;
            t = v2.x; v2.x = t * c4.z - v2.y * s4.z; v2.y = t * s4.z + v2.y * c4.z;
            t = v3.x; v3.x = t * c4.w - v3.y * s4.w; v3.y = t * s4.w + v3.y * c4.w;
        }
        float* Cp = C + (size_t)m * Dd + n0 + tx * 8;
        *(float4*)(Cp)     = make_float4(v0.x, v0.y, v1.x, v1.y);
        *(float4*)(Cp + 4) = make_float4(v2.x, v2.y, v3.x, v3.y);
    }
}

// ---------------------------------------------------------------------------
// Plain GEMM (output projection): out = A * W^T
// ---------------------------------------------------------------------------
__global__ void __launch_bounds__(256, 2) gemm_nt2(const float* __restrict__ A,
                                                   const float* __restrict__ W,
                                                   float* __restrict__ C) {
    __shared__ float Ast[16][128];
    __shared__ float Wst[16][128];

    const int tid = threadIdx.x;
    const int tx = tid & 15;
    const int ty = tid >> 4;
    const int m0 = blockIdx.y * 128;
    const int n0 = blockIdx.x * 128;

    ull acc2[8][4];
    gemm_core(A, W, m0, n0, tid, Ast, Wst, acc2);

#pragma unroll
    for (int i = 0; i < 8; i++) {
        float* Cp = C + (size_t)(m0 + ty * 8 + i) * Dd + n0 + tx * 8;
        *(ulonglong2*)(Cp)     = make_ulonglong2(acc2[i][0], acc2[i][1]);
        *(ulonglong2*)(Cp + 4) = make_ulonglong2(acc2[i][2], acc2[i][3]);
    }
}

// ---------------------------------------------------------------------------
// Flash-style causal attention, f32x2 inner loops.
// One CTA per (b, h, 64-query tile).  logits = q.k/64 folded into Q load.
// ---------------------------------------------------------------------------
__global__ void __launch_bounds__(256) flash_kernel(const float* __restrict__ Q,
                                                    const float* __restrict__ Kg,
                                                    const float* __restrict__ Vg,
                                                    float* __restrict__ Og) {
    __shared__ float qs[64][64];   // qs[row][dk], pre-scaled by 1/64
    __shared__ float kv[64][64];   // K phase: kv[dk][key]; V phase: kv[key][dk]
    __shared__ float ps[64][64];   // probabilities ps[row][key]

    const int tid = threadIdx.x;
    const int tx = tid & 15;
    const int ty = tid >> 4;
    const int tx4 = tx * 4, ty4 = ty * 4;

    const int qt = blockIdx.x & 31;
    const int h  = (blockIdx.x >> 5) & (Hh - 1);
    const int b  = blockIdx.x >> 9;

    // Load Q tile, folding the 1/64 logit scale
    {
        int r = tid >> 2, vb = tid & 3;
        const float* qp = Q + (((size_t)b * Ss + qt * 64 + r) * Hh + h) * DKk;
        const float sc = 1.0f / 64.0f;
#pragma unroll
        for (int u = vb; u < 16; u += 4) {
            float4 t4 = *(const float4*)(qp + u * 4);
            *(float4*)&qs[r][u * 4] =
                make_float4(t4.x * sc, t4.y * sc, t4.z * sc, t4.w * sc);
        }
    }

    float m_i[4], l_i[4];
    ull o2[4][2];
#pragma unroll
    for (int i = 0; i < 4; i++) {
        m_i[i] = -1e30f; l_i[i] = 0.0f;
        o2[i][0] = 0ull; o2[i][1] = 0ull;
    }
    __syncthreads();

    for (int kt = 0; kt <= qt; kt++) {
        const int k0 = kt * 64;
        // Load K tile transposed: kv[dk][key]
        {
            int r = tid >> 2, vb = tid & 3;
            const float* kp = Kg + (((size_t)b * Ss + k0 + r) * Hh + h) * DKk;
#pragma unroll
            for (int u = vb; u < 16; u += 4) {
                float4 t4 = *(const float4*)(kp + u * 4);
                kv[u * 4 + 0][r] = t4.x;
                kv[u * 4 + 1][r] = t4.y;
                kv[u * 4 + 2][r] = t4.z;
                kv[u * 4 + 3][r] = t4.w;
            }
        }
        __syncthreads();

        // S = Q * K^T  (4x4 micro-tile per thread, packed pairs over keys)
        ull s2[4][2];
#pragma unroll
        for (int i = 0; i < 4; i++) { s2[i][0] = 0ull; s2[i][1] = 0ull; }

#pragma unroll 16
        for (int dk = 0; dk < 64; dk++) {
            ulonglong2 b2 = *(const ulonglong2*)&kv[dk][tx4];
#pragma unroll
            for (int i = 0; i < 4; i++) {
                ull ad = dup2(qs[ty4 + i][dk]);
                ffma2(s2[i][0], ad, b2.x);
                ffma2(s2[i][1], ad, b2.y);
            }
        }

        // Unpack, causal-mask the diagonal tile
        float s[4][4];
        const bool diag = (kt == qt);
#pragma unroll
        for (int i = 0; i < 4; i++) {
            float2 pa = up2(s2[i][0]);
            float2 pb = up2(s2[i][1]);
            s[i][0] = pa.x; s[i][1] = pa.y; s[i][2] = pb.x; s[i][3] = pb.y;
            if (diag) {
                int rg = qt * 64 + ty4 + i;
#pragma unroll
                for (int j = 0; j < 4; j++)
                    if ((k0 + tx4 + j) > rg) s[i][j] = -1e30f;
            }
        }

        // Online softmax update; row reductions across the 16-lane row group.
#pragma unroll
        for (int i = 0; i < 4; i++) {
            float mx = fmaxf(fmaxf(s[i][0], s[i][1]), fmaxf(s[i][2], s[i][3]));
#pragma unroll
            for (int off = 1; off < 16; off <<= 1)
                mx = fmaxf(mx, __shfl_xor_sync(0xffffffffu, mx, off));
            float mnew = fmaxf(m_i[i], mx);
            float corr = __expf(m_i[i] - mnew);
            float rs = 0.0f;
#pragma unroll
            for (int j = 0; j < 4; j++) {
                float p = __expf(s[i][j] - mnew);
                s[i][j] = p;
                rs += p;
            }
#pragma unroll
            for (int off = 1; off < 16; off <<= 1)
                rs += __shfl_xor_sync(0xffffffffu, rs, off);
            l_i[i] = l_i[i] * corr + rs;
            m_i[i] = mnew;
            ull cd = dup2(corr);
            o2[i][0] = mul2(o2[i][0], cd);
            o2[i][1] = mul2(o2[i][1], cd);
            *(float4*)&ps[ty4 + i][tx4] = make_float4(s[i][0], s[i][1], s[i][2], s[i][3]);
        }
        __syncthreads();   // done reading K tile, P written

        // Load V tile (normal layout): kv[key][dk]
        {
            int r = tid >> 2, vb = tid & 3;
            const float* vp = Vg + (((size_t)b * Ss + k0 + r) * Hh + h) * DKk;
#pragma unroll
            for (int u = vb; u < 16; u += 4)
                *(float4*)&kv[r][u * 4] = *(const float4*)(vp + u * 4);
        }
        __syncthreads();

        // O += P * V  (packed pairs over dk)
#pragma unroll 16
        for (int kk = 0; kk < 64; kk++) {
            ulonglong2 v2 = *(const ulonglong2*)&kv[kk][tx4];
#pragma unroll
            for (int i = 0; i < 4; i++) {
                ull pd = dup2(ps[ty4 + i][kk]);
                ffma2(o2[i][0], pd, v2.x);
                ffma2(o2[i][1], pd, v2.y);
            }
        }
        __syncthreads();   // before next iteration overwrites kv / ps
    }

    // Normalize and write out (layout [B,S,H,DK] == [B,S,D])
#pragma unroll
    for (int i = 0; i < 4; i++) {
        float inv = 1.0f / l_i[i];
        float2 a = up2(o2[i][0]);
        float2 c = up2(o2[i][1]);
        float* op = Og + (((size_t)b * Ss + qt * 64 + ty4 + i) * Hh + h) * DKk + tx4;
        *(float4*)op = make_float4(a.x * inv, a.y * inv, c.x * inv, c.y * inv);
    }
}

// ---------------------------------------------------------------------------
// Launch: x,fc,fs,mask,wq,wk,wv,wo  (mask is analytic causal -> unused)
// ---------------------------------------------------------------------------
extern "C" void kernel_launch(void* const* d_in, const int* in_sizes, int n_in,
                              void* d_out, int out_size) {
    const float* x  = (const float*)d_in[0];
    const float* fc = (const float*)d_in[1];
    const float* fs = (const float*)d_in[2];
    const float* wq = (const float*)d_in[4];
    const float* wk = (const float*)d_in[5];
    const float* wv = (const float*)d_in[6];
    const float* wo = (const float*)d_in[7];
    float* out = (float*)d_out;

    float *q, *k, *v, *ao;
    cudaGetSymbolAddress((void**)&q,  g_q);
    cudaGetSymbolAddress((void**)&k,  g_k);
    cudaGetSymbolAddress((void**)&v,  g_v);
    cudaGetSymbolAddress((void**)&ao, g_ao);

    gemm_qkv<<<dim3(8, 32, 3), 256>>>(x, wq, wk, wv, q, k, v, fc, fs);

    flash_kernel<<<Bb * Hh * (Ss / 64), 256>>>(q, k, v, ao);

    gemm_nt2<<<dim3(8, 32), 256>>>(ao, wo, out);
}

// round 7
// speedup vs baseline: 1.0902x; 1.0335x over previous
#include <cuda_runtime.h>

// Problem constants
#define Bb 2
#define Ss 2048
#define Dd 1024
#define Hh 16
#define DKk 64

typedef unsigned long long ull;

// Scratch (allocation-free rule: __device__ globals)
__device__ float g_q [(size_t)Bb * Ss * Dd];
__device__ float g_k [(size_t)Bb * Ss * Dd];
__device__ float g_v [(size_t)Bb * Ss * Dd];
__device__ float g_ao[(size_t)Bb * Ss * Dd];

// ---------------------------------------------------------------------------
// Packed f32x2 helpers
// ---------------------------------------------------------------------------
__device__ __forceinline__ ull dup2(float x) {
    ull r;
    asm("mov.b64 %0, {%1, %1};" : "=l"(r) : "r"(__float_as_uint(x)));
    return r;
}
__device__ __forceinline__ void ffma2(ull& d, ull a, ull b) {
    asm("fma.rn.f32x2 %0, %1, %2, %0;" : "+l"(d) : "l"(a), "l"(b));
}
__device__ __forceinline__ ull mul2(ull a, ull b) {
    ull r;
    asm("mul.rn.f32x2 %0, %1, %2;" : "=l"(r) : "l"(a), "l"(b));
    return r;
}
__device__ __forceinline__ float2 up2(ull v) {
    unsigned lo, hi;
    asm("mov.b64 {%0, %1}, %2;" : "=r"(lo), "=r"(hi) : "l"(v));
    return make_float2(__uint_as_float(lo), __uint_as_float(hi));
}
__device__ __forceinline__ float f4e(const float4& v, int t) {
    return (&v.x)[t];   // folded statically under #pragma unroll
}

// ---------------------------------------------------------------------------
// GEMM core: C[M,N] = A[M,1024] * W[N,1024]^T, 128x128 tile, BK=16,
// 256 threads, 8x8 micro-tile via f32x2, DOUBLE-BUFFERED smem:
// one __syncthreads per k-step, global prefetch overlapped with compute.
// ---------------------------------------------------------------------------
__device__ __forceinline__ void gemm_core(const float* __restrict__ A,
                                          const float* __restrict__ W,
                                          int m0, int n0, int tid,
                                          float (*Ast)[16][128],
                                          float (*Wst)[16][128],
                                          ull acc2[8][4]) {
    const int tx = tid & 15;
    const int ty = tid >> 4;
    const int lr = tid >> 1;        // 0..127: row within tile
    const int lc = (tid & 1) * 8;   // 0 or 8: k-offset within BK=16

    const float* Ap = A + (size_t)(m0 + lr) * Dd + lc;
    const float* Wp = W + (size_t)(n0 + lr) * Dd + lc;

#pragma unroll
    for (int i = 0; i < 8; i++)
#pragma unroll
        for (int j = 0; j < 4; j++) acc2[i][j] = 0ull;

    float4 a0 = *(const float4*)(Ap);
    float4 a1 = *(const float4*)(Ap + 4);
    float4 w0 = *(const float4*)(Wp);
    float4 w1 = *(const float4*)(Wp + 4);

    // fill buffer 0
    {
        float* As = &Ast[0][lc][lr];
        float* Ws = &Wst[0][lc][lr];
        As[0*128] = a0.x; As[1*128] = a0.y; As[2*128] = a0.z; As[3*128] = a0.w;
        As[4*128] = a1.x; As[5*128] = a1.y; As[6*128] = a1.z; As[7*128] = a1.w;
        Ws[0*128] = w0.x; Ws[1*128] = w0.y; Ws[2*128] = w0.z; Ws[3*128] = w0.w;
        Ws[4*128] = w1.x; Ws[5*128] = w1.y; Ws[6*128] = w1.z; Ws[7*128] = w1.w;
    }
    __syncthreads();

#pragma unroll 1
    for (int it = 0; it < 64; it++) {
        const int cur = it & 1;
        // prefetch next k-block (LDG in flight during compute)
        if (it < 63) {
            const float* Ap2 = Ap + (it + 1) * 16;
            const float* Wp2 = Wp + (it + 1) * 16;
            a0 = *(const float4*)(Ap2);
            a1 = *(const float4*)(Ap2 + 4);
            w0 = *(const float4*)(Wp2);
            w1 = *(const float4*)(Wp2 + 4);
        }

#pragma unroll
        for (int kk = 0; kk < 16; kk++) {
            float a[8];
            *(float4*)&a[0] = *(const float4*)&Ast[cur][kk][ty * 8];
            *(float4*)&a[4] = *(const float4*)&Ast[cur][kk][ty * 8 + 4];
            ulonglong2 wp0 = *(const ulonglong2*)&Wst[cur][kk][tx * 8];
            ulonglong2 wp1 = *(const ulonglong2*)&Wst[cur][kk][tx * 8 + 4];
#pragma unroll
            for (int i = 0; i < 8; i++) {
                ull ad = dup2(a[i]);
                ffma2(acc2[i][0], ad, wp0.x);
                ffma2(acc2[i][1], ad, wp0.y);
                ffma2(acc2[i][2], ad, wp1.x);
                ffma2(acc2[i][3], ad, wp1.y);
            }
        }

        // store prefetched block into the other buffer
        if (it < 63) {
            float* As = &Ast[cur ^ 1][lc][lr];
            float* Ws = &Wst[cur ^ 1][lc][lr];
            As[0*128] = a0.x; As[1*128] = a0.y; As[2*128] = a0.z; As[3*128] = a0.w;
            As[4*128] = a1.x; As[5*128] = a1.y; As[6*128] = a1.z; As[7*128] = a1.w;
            Ws[0*128] = w0.x; Ws[1*128] = w0.y; Ws[2*128] = w0.z; Ws[3*128] = w0.w;
            Ws[4*128] = w1.x; Ws[5*128] = w1.y; Ws[6*128] = w1.z; Ws[7*128] = w1.w;
        }
        __syncthreads();
    }
}

// ---------------------------------------------------------------------------
// Fused QKV projection + RoPE epilogue.  blockIdx.z: 0=Q(rope) 1=K(rope) 2=V.
// ---------------------------------------------------------------------------
__global__ void __launch_bounds__(256, 2) gemm_qkv(const float* __restrict__ x,
                                                   const float* __restrict__ wq,
                                                   const float* __restrict__ wk,
                                                   const float* __restrict__ wv,
                                                   float* __restrict__ q,
                                                   float* __restrict__ k,
                                                   float* __restrict__ v,
                                                   const float* __restrict__ cs,
                                                   const float* __restrict__ sn) {
    __shared__ float Ast[2][16][128];
    __shared__ float Wst[2][16][128];

    const int z = blockIdx.z;
    const float* W = (z == 0) ? wq : ((z == 1) ? wk : wv);
    float* C = (z == 0) ? q : ((z == 1) ? k : v);

    const int tid = threadIdx.x;
    const int tx = tid & 15;
    const int ty = tid >> 4;
    const int m0 = blockIdx.y * 128;
    const int n0 = blockIdx.x * 128;

    ull acc2[8][4];
    gemm_core(x, W, m0, n0, tid, Ast, Wst, acc2);

    const bool dorope = (z < 2);
    const int p0 = (tx & 7) * 4;   // pair base within head (cols are head-aligned)

#pragma unroll
    for (int i = 0; i < 8; i++) {
        const int m = m0 + ty * 8 + i;
        float2 v0 = up2(acc2[i][0]);
        float2 v1 = up2(acc2[i][1]);
        float2 v2 = up2(acc2[i][2]);
        float2 v3 = up2(acc2[i][3]);
        if (dorope) {
            const int s = m & (Ss - 1);
            float4 c4 = *(const float4*)(cs + (size_t)s * 32 + p0);
            float4 s4 = *(const float4*)(sn + (size_t)s * 32 + p0);
            float t;
            t = v0.x; v0.x = t * c4.x - v0.y * s4.x; v0.y = t * s4.x + v0.y * c4.x;
            t = v1.x; v1.x = t * c4.y - v1.y * s4.y; v1.y = t * s4.y + v1.y * c4.y;
            t = v2.x; v2.x = t * c4.z - v2.y * s4.z; v2.y = t * s4.z + v2.y * c4.z;
            t = v3.x; v3.x = t * c4.w - v3.y * s4.w; v3.y = t * s4.w + v3.y * c4.w;
        }
        float* Cp = C + (size_t)m * Dd + n0 + tx * 8;
        *(float4*)(Cp)     = make_float4(v0.x, v0.y, v1.x, v1.y);
        *(float4*)(Cp + 4) = make_float4(v2.x, v2.y, v3.x, v3.y);
    }
}

// ---------------------------------------------------------------------------
// Plain GEMM (output projection): out = A * W^T
// ---------------------------------------------------------------------------
__global__ void __launch_bounds__(256, 2) gemm_nt2(const float* __restrict__ A,
                                                   const float* __restrict__ W,
                                                   float* __restrict__ C) {
    __shared__ float Ast[2][16][128];
    __shared__ float Wst[2][16][128];

    const int tid = threadIdx.x;
    const int tx = tid & 15;
    const int ty = tid >> 4;
    const int m0 = blockIdx.y * 128;
    const int n0 = blockIdx.x * 128;

    ull acc2[8][4];
    gemm_core(A, W, m0, n0, tid, Ast, Wst, acc2);

#pragma unroll
    for (int i = 0; i < 8; i++) {
        float* Cp = C + (size_t)(m0 + ty * 8 + i) * Dd + n0 + tx * 8;
        *(ulonglong2*)(Cp)     = make_ulonglong2(acc2[i][0], acc2[i][1]);
        *(ulonglong2*)(Cp + 4) = make_ulonglong2(acc2[i][2], acc2[i][3]);
    }
}

// ---------------------------------------------------------------------------
// Flash-style causal attention.
// 64KB dynamic smem: qs | kt | vs | ps.  2 barriers per k-tile.
// Inner loops unrolled x4 with float4 row-operand loads.
// ---------------------------------------------------------------------------
__global__ void __launch_bounds__(256) flash_kernel(const float* __restrict__ Q,
                                                    const float* __restrict__ Kg,
                                                    const float* __restrict__ Vg,
                                                    float* __restrict__ Og) {
    extern __shared__ float fsm[];
    float (*qs)[64] = (float (*)[64])(fsm);           // [row][dk], pre-scaled
    float (*kt)[64] = (float (*)[64])(fsm + 4096);    // [dk][key]  (transposed)
    float (*vs)[64] = (float (*)[64])(fsm + 8192);    // [key][dk]
    float (*ps)[64] = (float (*)[64])(fsm + 12288);   // [row][key]

    const int tid = threadIdx.x;
    const int tx = tid & 15;
    const int ty = tid >> 4;
    const int tx4 = tx * 4, ty4 = ty * 4;

    const int qt = blockIdx.x & 31;
    const int h  = (blockIdx.x >> 5) & (Hh - 1);
    const int b  = blockIdx.x >> 9;

    const int r  = tid >> 2;      // 0..63: tile row handled by this thread
    const int vb = tid & 3;       // float4 slot offset

    // Load Q tile, folding the 1/64 logit scale
    {
        const float* qp = Q + (((size_t)b * Ss + qt * 64 + r) * Hh + h) * DKk;
        const float sc = 1.0f / 64.0f;
#pragma unroll
        for (int u = vb; u < 16; u += 4) {
            float4 t4 = *(const float4*)(qp + u * 4);
            *(float4*)&qs[r][u * 4] =
                make_float4(t4.x * sc, t4.y * sc, t4.z * sc, t4.w * sc);
        }
    }

    float m_i[4], l_i[4];
    ull o2[4][2];
#pragma unroll
    for (int i = 0; i < 4; i++) {
        m_i[i] = -1e30f; l_i[i] = 0.0f;
        o2[i][0] = 0ull; o2[i][1] = 0ull;
    }

#pragma unroll 1
    for (int kti = 0; kti <= qt; kti++) {
        const int k0 = kti * 64;

        // K tile -> kt transposed (LDG + scattered STS)
        {
            const float* kp = Kg + (((size_t)b * Ss + k0 + r) * Hh + h) * DKk;
#pragma unroll
            for (int u = vb; u < 16; u += 4) {
                float4 t4 = *(const float4*)(kp + u * 4);
                kt[u * 4 + 0][r] = t4.x;
                kt[u * 4 + 1][r] = t4.y;
                kt[u * 4 + 2][r] = t4.z;
                kt[u * 4 + 3][r] = t4.w;
            }
        }
        // V tile prefetch into registers (LDG in flight through QK phase)
        float4 vreg[4];
        {
            const float* vp = Vg + (((size_t)b * Ss + k0 + r) * Hh + h) * DKk;
#pragma unroll
            for (int u = 0; u < 4; u++)
                vreg[u] = *(const float4*)(vp + (vb + u * 4) * 4);
        }
        __syncthreads();   // (A) kt ready; prev PV fully drained

        // S = Q * K^T : dk unrolled x4, float4 q-row loads
        ull s2[4][2];
#pragma unroll
        for (int i = 0; i < 4; i++) { s2[i][0] = 0ull; s2[i][1] = 0ull; }

#pragma unroll 4
        for (int dk = 0; dk < 64; dk += 4) {
            float4 q0 = *(const float4*)&qs[ty4 + 0][dk];
            float4 q1 = *(const float4*)&qs[ty4 + 1][dk];
            float4 q2 = *(const float4*)&qs[ty4 + 2][dk];
            float4 q3 = *(const float4*)&qs[ty4 + 3][dk];
#pragma unroll
            for (int t = 0; t < 4; t++) {
                ulonglong2 k2 = *(const ulonglong2*)&kt[dk + t][tx4];
                ffma2(s2[0][0], dup2(f4e(q0, t)), k2.x);
                ffma2(s2[0][1], dup2(f4e(q0, t)), k2.y);
                ffma2(s2[1][0], dup2(f4e(q1, t)), k2.x);
                ffma2(s2[1][1], dup2(f4e(q1, t)), k2.y);
                ffma2(s2[2][0], dup2(f4e(q2, t)), k2.x);
                ffma2(s2[2][1], dup2(f4e(q2, t)), k2.y);
                ffma2(s2[3][0], dup2(f4e(q3, t)), k2.x);
                ffma2(s2[3][1], dup2(f4e(q3, t)), k2.y);
            }
        }

        // Unpack + causal mask on the diagonal tile
        float s[4][4];
        const bool diag = (kti == qt);
#pragma unroll
        for (int i = 0; i < 4; i++) {
            float2 pa = up2(s2[i][0]);
            float2 pb = up2(s2[i][1]);
            s[i][0] = pa.x; s[i][1] = pa.y; s[i][2] = pb.x; s[i][3] = pb.y;
            if (diag) {
                int rg = qt * 64 + ty4 + i;
#pragma unroll
                for (int j = 0; j < 4; j++)
                    if ((k0 + tx4 + j) > rg) s[i][j] = -1e30f;
            }
        }

        // Online softmax update (row spread over 16 lanes)
#pragma unroll
        for (int i = 0; i < 4; i++) {
            float mx = fmaxf(fmaxf(s[i][0], s[i][1]), fmaxf(s[i][2], s[i][3]));
#pragma unroll
            for (int off = 1; off < 16; off <<= 1)
                mx = fmaxf(mx, __shfl_xor_sync(0xffffffffu, mx, off));
            float mnew = fmaxf(m_i[i], mx);
            float corr = __expf(m_i[i] - mnew);
            float rs = 0.0f;
#pragma unroll
            for (int j = 0; j < 4; j++) {
                float p = __expf(s[i][j] - mnew);
                s[i][j] = p;
                rs += p;
            }
#pragma unroll
            for (int off = 1; off < 16; off <<= 1)
                rs += __shfl_xor_sync(0xffffffffu, rs, off);
            l_i[i] = l_i[i] * corr + rs;
            m_i[i] = mnew;
            ull cd = dup2(corr);
            o2[i][0] = mul2(o2[i][0], cd);
            o2[i][1] = mul2(o2[i][1], cd);
            *(float4*)&ps[ty4 + i][tx4] = make_float4(s[i][0], s[i][1], s[i][2], s[i][3]);
        }

        // V registers -> vs
#pragma unroll
        for (int u = 0; u < 4; u++)
            *(float4*)&vs[r][(vb + u * 4) * 4] = vreg[u];

        __syncthreads();   // (B) ps + vs ready; kt reads complete

        // O += P * V : kk unrolled x4, float4 p-row loads
#pragma unroll 4
        for (int kk = 0; kk < 64; kk += 4) {
            float4 p0 = *(const float4*)&ps[ty4 + 0][kk];
            float4 p1 = *(const float4*)&ps[ty4 + 1][kk];
            float4 p2 = *(const float4*)&ps[ty4 + 2][kk];
            float4 p3 = *(const float4*)&ps[ty4 + 3][kk];
#pragma unroll
            for (int t = 0; t < 4; t++) {
                ulonglong2 v2 = *(const ulonglong2*)&vs[kk + t][tx4];
                ffma2(o2[0][0], dup2(f4e(p0, t)), v2.x);
                ffma2(o2[0][1], dup2(f4e(p0, t)), v2.y);
                ffma2(o2[1][0], dup2(f4e(p1, t)), v2.x);
                ffma2(o2[1][1], dup2(f4e(p1, t)), v2.y);
                ffma2(o2[2][0], dup2(f4e(p2, t)), v2.x);
                ffma2(o2[2][1], dup2(f4e(p2, t)), v2.y);
                ffma2(o2[3][0], dup2(f4e(p3, t)), v2.x);
                ffma2(o2[3][1], dup2(f4e(p3, t)), v2.y);
            }
        }
        // no trailing sync: next iter writes only kt (disjoint from ps/vs),
        // and its ps/vs writes happen after sync (A).
    }

    // Normalize and write out (layout [B,S,H,DK] == [B,S,D])
#pragma unroll
    for (int i = 0; i < 4; i++) {
        float inv = 1.0f / l_i[i];
        float2 a = up2(o2[i][0]);
        float2 c = up2(o2[i][1]);
        float* op = Og + (((size_t)b * Ss + qt * 64 + ty4 + i) * Hh + h) * DKk + tx4;
        *(float4*)op = make_float4(a.x * inv, a.y * inv, c.x * inv, c.y * inv);
    }
}

// ---------------------------------------------------------------------------
// Launch: x,fc,fs,mask,wq,wk,wv,wo  (mask is analytic causal -> unused)
// ---------------------------------------------------------------------------
extern "C" void kernel_launch(void* const* d_in, const int* in_sizes, int n_in,
                              void* d_out, int out_size) {
    const float* x  = (const float*)d_in[0];
    const float* fc = (const float*)d_in[1];
    const float* fs = (const float*)d_in[2];
    const float* wq = (const float*)d_in[4];
    const float* wk = (const float*)d_in[5];
    const float* wv = (const float*)d_in[6];
    const float* wo = (const float*)d_in[7];
    float* out = (float*)d_out;

    float *q, *k, *v, *ao;
    cudaGetSymbolAddress((void**)&q,  g_q);
    cudaGetSymbolAddress((void**)&k,  g_k);
    cudaGetSymbolAddress((void**)&v,  g_v);
    cudaGetSymbolAddress((void**)&ao, g_ao);

    // Unconditional (idempotent, host-side, capture-safe): no static guards.
    cudaFuncSetAttribute(flash_kernel,
                         cudaFuncAttributeMaxDynamicSharedMemorySize, 65536);

    gemm_qkv<<<dim3(8, 32, 3), 256>>>(x, wq, wk, wv, q, k, v, fc, fs);

    flash_kernel<<<Bb * Hh * (Ss / 64), 256, 65536>>>(q, k, v, ao);

    gemm_nt2<<<dim3(8, 32), 256>>>(ao, wo, out);
}